// round 5
// baseline (speedup 1.0000x reference)
#include <cuda_runtime.h>
#include <cuda_bf16.h>

#define TLEN 2048
#define CH 32
#define NC 64                       // chunks per sequence
#define BPB 2                       // batches per block
#define NTHREADS 128

struct M2 { float a, b, c, d; };
__device__ __forceinline__ M2 mmul(M2 X, M2 Y) {   // X*Y
    M2 r;
    r.a = fmaf(X.a, Y.a, X.b * Y.c);
    r.b = fmaf(X.a, Y.b, X.b * Y.d);
    r.c = fmaf(X.c, Y.a, X.d * Y.c);
    r.d = fmaf(X.c, Y.b, X.d * Y.d);
    return r;
}

__global__ __launch_bounds__(NTHREADS) void physics_scan_kernel(
    const float* __restrict__ u,
    const float* __restrict__ p_dt, const float* __restrict__ p_m,
    const float* __restrict__ p_c,  const float* __restrict__ p_k,
    const float* __restrict__ p_im, const float* __restrict__ p_is,
    const float* __restrict__ p_om, const float* __restrict__ p_os,
    float* __restrict__ out, int Bsz)
{
    __shared__ float2 sab[CH];      // (alpha_i, beta_i) = (q1,q2)*A^{i+1}
    __shared__ float2 swtot[BPB];   // first-half-warp inclusive totals

    const int tid  = threadIdx.x;
    const int lane = tid & 31;
    const int lb   = tid >> 6;          // batch within block
    const int h    = (tid >> 5) & 1;    // which half of the 64 chunks
    const int c    = (h << 5) + lane;   // chunk id 0..63

    const float dt = *p_dt, m = *p_m, cc = *p_c, k = *p_k;
    const float in_mean = *p_im, in_std = *p_is;
    const float out_mean = *p_om, out_std = *p_os;
    const float inv_m = 1.0f / m;
    const float ios   = 1.0f / out_std;
    const float a1 = -k * inv_m;
    const float a2 = -cc * inv_m;
    const float s1 = in_std * inv_m;      // g = u*s1 + s0  (= u_p/m)
    const float s0 = in_mean * inv_m;
    const float q1 = a1 * ios, q2 = a2 * ios, q0 = -out_mean * ios;

    M2 A; A.a = 1.0f; A.b = dt; A.c = dt * a1; A.d = 1.0f + dt * a2;

    // recurrence folded: v' = Ac*x + Ad*v + (dt*g),  x' = x + dt*v
    const float gd1 = dt * s1, gd0 = dt * s0;         // dt*g = u*gd1 + gd0
    const float r1  = ios * s1;                       // ios*g + q0 = u*r1 + r0
    const float r0  = fmaf(ios, s0, q0);

    // ---- (alpha,beta) table: lane i of warp 0 computes (q1,q2)*A^{i+1} ----
    if (tid < 32) {
        M2 Q = A;
        M2 M; M.a = 1.f; M.b = 0.f; M.c = 0.f; M.d = 1.f;
        int e = lane + 1;
        #pragma unroll
        for (int b2 = 0; b2 < 6; b2++) {
            if (e & (1 << b2)) M = mmul(Q, M);
            if (b2 < 5) Q = mmul(Q, Q);
        }
        sab[lane] = make_float2(fmaf(q1, M.a, q2 * M.c),
                                fmaf(q1, M.b, q2 * M.d));
    }

    const size_t goff = (size_t)blockIdx.x * (BPB * TLEN)
                      + (size_t)lb * TLEN + (size_t)c * CH;

    // ---- Load this thread's chunk into registers (8x LDG.128) ----
    const float4* gu = reinterpret_cast<const float4*>(u + goff);
    float4 U[8];
    #pragma unroll
    for (int i = 0; i < 8; i++) U[i] = gu[i];

    // ---- Pass 1: chunk recurrence from zero state; y0 replaces u in regs ----
    float x = 0.0f, v = 0.0f;
    #pragma unroll
    for (int i4 = 0; i4 < 8; i4++) {
        float4 uu = U[i4];
        float4 yy;
        {
            float g2 = fmaf(uu.x, gd1, gd0);
            float vn = fmaf(A.c, x, fmaf(A.d, v, g2));
            float xn = fmaf(dt, v, x);
            x = xn; v = vn;
            yy.x = fmaf(q1, x, fmaf(q2, v, fmaf(uu.x, r1, r0)));
        }
        {
            float g2 = fmaf(uu.y, gd1, gd0);
            float vn = fmaf(A.c, x, fmaf(A.d, v, g2));
            float xn = fmaf(dt, v, x);
            x = xn; v = vn;
            yy.y = fmaf(q1, x, fmaf(q2, v, fmaf(uu.y, r1, r0)));
        }
        {
            float g2 = fmaf(uu.z, gd1, gd0);
            float vn = fmaf(A.c, x, fmaf(A.d, v, g2));
            float xn = fmaf(dt, v, x);
            x = xn; v = vn;
            yy.z = fmaf(q1, x, fmaf(q2, v, fmaf(uu.z, r1, r0)));
        }
        {
            float g2 = fmaf(uu.w, gd1, gd0);
            float vn = fmaf(A.c, x, fmaf(A.d, v, g2));
            float xn = fmaf(dt, v, x);
            x = xn; v = vn;
            yy.w = fmaf(q1, x, fmaf(q2, v, fmaf(uu.w, r1, r0)));
        }
        U[i4] = yy;
    }

    // ---- Power chain: P[s] = (A^32)^(2^s) ----
    M2 P[5];
    {
        M2 Q = A;
        #pragma unroll
        for (int s = 0; s < 5; s++) Q = mmul(Q, Q);   // A^32
        P[0] = Q;
        #pragma unroll
        for (int s = 1; s < 5; s++) P[s] = mmul(P[s - 1], P[s - 1]);
    }

    // ---- Warp Kogge-Stone scan of chunk offsets (matrix is lane-common) ----
    float bx = x, bv = v;
    #pragma unroll
    for (int s = 0; s < 5; s++) {
        int d = 1 << s;
        float ox = __shfl_up_sync(0xffffffffu, bx, d);
        float ov = __shfl_up_sync(0xffffffffu, bv, d);
        if (lane >= d) {
            bx = fmaf(P[s].a, ox, fmaf(P[s].b, ov, bx));
            bv = fmaf(P[s].c, ox, fmaf(P[s].d, ov, bv));
        }
    }
    float ex = __shfl_up_sync(0xffffffffu, bx, 1);
    float ev = __shfl_up_sync(0xffffffffu, bv, 1);
    if (lane == 0) { ex = 0.0f; ev = 0.0f; }

    if (h == 0 && lane == 31) swtot[lb] = make_float2(bx, bv);
    __syncthreads();   // publishes swtot AND sab

    // ---- Cross-warp fix-up: this thread now holds its chunk's start state ----
    float sx = ex, sv = ev;
    if (h == 1) {
        float2 t = swtot[lb];
        float wx = t.x, wv = t.y;     // (A^32)^lane * s_in via bit products
        #pragma unroll
        for (int b2 = 0; b2 < 5; b2++) {
            if (lane & (1 << b2)) {
                float nx = fmaf(P[b2].a, wx, P[b2].b * wv);
                float nv = fmaf(P[b2].c, wx, P[b2].d * wv);
                wx = nx; wv = nv;
            }
        }
        sx += wx; sv += wv;
        if (lane == 31) {             // final state s_T = b_inc + (A^32)^32 * s_in
            M2 P5 = mmul(P[4], P[4]);
            float fx = fmaf(P5.a, t.x, fmaf(P5.b, t.y, bx));
            float fv = fmaf(P5.c, t.x, fmaf(P5.d, t.y, bv));
            float2* stout = reinterpret_cast<float2*>(out + (size_t)Bsz * TLEN);
            stout[blockIdx.x * BPB + lb] = make_float2(fx, fv);
        }
    }

    // ---- Writeout with fused affine correction: y = y0 + (a,b)·s_start ----
    float4* gy = reinterpret_cast<float4*>(out + goff);
    const float4* abv = reinterpret_cast<const float4*>(sab);
    #pragma unroll
    for (int i4 = 0; i4 < 8; i4++) {
        float4 ab01 = abv[2 * i4];       // (a,b) for elems 4*i4, 4*i4+1  (broadcast)
        float4 ab23 = abv[2 * i4 + 1];   // (a,b) for elems 4*i4+2, 4*i4+3
        float4 y0 = U[i4];
        float4 yy;
        yy.x = fmaf(ab01.x, sx, fmaf(ab01.y, sv, y0.x));
        yy.y = fmaf(ab01.z, sx, fmaf(ab01.w, sv, y0.y));
        yy.z = fmaf(ab23.x, sx, fmaf(ab23.y, sv, y0.z));
        yy.w = fmaf(ab23.z, sx, fmaf(ab23.w, sv, y0.w));
        gy[i4] = yy;
    }
}

extern "C" void kernel_launch(void* const* d_in, const int* in_sizes, int n_in,
                              void* d_out, int out_size) {
    const float* u = (const float*)d_in[0];
    int Bsz = in_sizes[0] / TLEN;
    dim3 grid(Bsz / BPB);
    physics_scan_kernel<<<grid, NTHREADS>>>(
        u,
        (const float*)d_in[1], (const float*)d_in[2], (const float*)d_in[3],
        (const float*)d_in[4], (const float*)d_in[5], (const float*)d_in[6],
        (const float*)d_in[7], (const float*)d_in[8],
        (float*)d_out, Bsz);
}